// round 15
// baseline (speedup 1.0000x reference)
#include <cuda_runtime.h>
#include <cuda_bf16.h>
#include <cuda_fp16.h>
#include <cstdint>

// ---------------- problem constants ----------------
#define S_TOT   8192
#define DK      1024            // K
#define NRULES  64
#define OPER    64
#define RO      (NRULES*OPER)   // 4096

// ---------------- tiling ----------------
#define BM      128             // CTA M tile
#define BN      128             // CTA N tile (= 2 rules)
#define KC      64              // K per chunk (fp16)
#define NCHUNK  (DK/KC)         // 16
#define NGRP    (RO/BN)         // 32 rule-groups
#define MTILES  (S_TOT/BM)      // 64
#define NSTAGE  3
#define STAGE   32768           // bytes per stage (A 16K + B 16K)
#define SMEM_SZ (NSTAGE*STAGE)  // 98304 -> 2 CTAs/SM

// ---------------- scratch ----------------
__device__ __half g_Xb[(size_t)S_TOT*DK];            // 16 MB (fp16)
__device__ __half g_Wb[(size_t)RO*DK];               // 8 MB  (fp16)
__device__ __half g_Ypart[(size_t)NGRP*S_TOT*OPER];  // 32 MB (fp16 partials)
__device__ int    g_cnt[MTILES];                     // per-mtile arrival counter

// ---------------- helpers ----------------
__device__ __forceinline__ uint32_t smem_u32(const void* p) {
    uint32_t a;
    asm("{ .reg .u64 t; cvta.to.shared.u64 t, %1; cvt.u32.u64 %0, t; }" : "=r"(a) : "l"(p));
    return a;
}
__device__ __forceinline__ void cp16_cg(uint32_t dst, const void* src) {   // L1 bypass
    asm volatile("cp.async.cg.shared.global [%0], [%1], 16;" :: "r"(dst), "l"(src));
}
__device__ __forceinline__ void cp_commit() {
    asm volatile("cp.async.commit_group;" ::: "memory");
}
template <int N>
__device__ __forceinline__ void cp_wait() {
    asm volatile("cp.async.wait_group %0;" :: "n"(N) : "memory");
}
__device__ __forceinline__ void ldsm_x4(uint32_t* r, uint32_t addr) {
    asm volatile("ldmatrix.sync.aligned.m8n8.x4.shared.b16 {%0,%1,%2,%3}, [%4];"
        : "=r"(r[0]), "=r"(r[1]), "=r"(r[2]), "=r"(r[3]) : "r"(addr));
}
// fp16-accumulate HMMA: D,C are 2x .f16x2 regs
__device__ __forceinline__ void mma16816_f16(uint32_t* c, const uint32_t* a,
                                             uint32_t b0, uint32_t b1) {
    asm volatile("mma.sync.aligned.m16n8k16.row.col.f16.f16.f16.f16 "
        "{%0,%1}, {%2,%3,%4,%5}, {%6,%7}, {%0,%1};"
        : "+r"(c[0]), "+r"(c[1])
        : "r"(a[0]), "r"(a[1]), "r"(a[2]), "r"(a[3]), "r"(b0), "r"(b1));
}
// sigmoid(x) = 0.5*tanh(0.5x) + 0.5  -> 1 MUFU + FMA
__device__ __forceinline__ float fast_sigmoid(float x) {
    float t;
    float h = 0.5f * x;
    asm("tanh.approx.f32 %0, %1;" : "=f"(t) : "f"(h));
    return fmaf(0.5f, t, 0.5f);
}

// ---------------- conversion kernel (fp32 -> fp16, MLP=8) ----------------
#define NX4 ((size_t)S_TOT*DK/4)       // 2097152 float4 in X
#define NW4 ((size_t)RO*DK/4)          // 1048576 float4 in W
#define WX_CVT (NX4/256)               // 8192 warps for X
#define WW_CVT (NW4/256)               // 4096 warps for W
#define CVT_BLOCKS ((unsigned)((WX_CVT + WW_CVT) / 8))   // 1536 blocks of 8 warps

__device__ __forceinline__ uint32_t pack_h2(float a, float b) {
    __half2 h = __floats2half2_rn(a, b);
    return *(uint32_t*)&h;
}
__global__ void __launch_bounds__(256)
cvt_kernel(const float4* __restrict__ X4, const float4* __restrict__ W4) {
    // reset the per-mtile arrival counters for this launch / graph replay
    if (blockIdx.x == 0 && threadIdx.x < MTILES) g_cnt[threadIdx.x] = 0;

    size_t t = (size_t)blockIdx.x * 256 + threadIdx.x;
    size_t w = t >> 5;
    int lane = (int)(t & 31);
    const float4* src;
    __half* dst;
    size_t base;
    if (w < WX_CVT) { src = X4; dst = g_Xb; base = w * 256; }
    else            { src = W4; dst = g_Wb; base = (w - WX_CVT) * 256; }

    float4 v[8];
#pragma unroll
    for (int i = 0; i < 8; i++) v[i] = src[base + lane + 32 * i];

    uint2* d = (uint2*)dst;   // uint2 index == float4 index
#pragma unroll
    for (int i = 0; i < 8; i++) {
        uint2 o;
        o.x = pack_h2(v[i].x, v[i].y);
        o.y = pack_h2(v[i].z, v[i].w);
        d[base + lane + 32 * i] = o;
    }
}

// ---------------- fused GEMM + sigmoid + lambda + tail reduction ----------------
__global__ void __launch_bounds__(256, 2)
somfnn_gemm(const float* __restrict__ bias, const float* __restrict__ lambdas,
            float* __restrict__ out) {
    extern __shared__ __align__(1024) char smem[];
    const uint32_t sb = smem_u32(smem);
    const int tid = threadIdx.x;
    const int wid = tid >> 5;
    const int lid = tid & 31;
    const int mw  = wid >> 2;        // 0..1 (M warps)
    const int nw  = wid & 3;         // 0..3 (N warps)
    const int m0  = blockIdx.x * BM;
    const int rg  = blockIdx.y;      // 0..31
    const int n0  = rg * BN;

    // ---- cp.async load of one K-chunk into stage buf (all .cg) ----
    auto load_chunk = [&](int kc, int buf) {
        const size_t kcol = (size_t)kc * KC;
        const uint32_t sbase = sb + buf * STAGE;
#pragma unroll
        for (int i = 0; i < 4; i++) {
            int v = tid + i * 256;       // 0..1023
            int row = v >> 3, w = v & 7;
            const void* src = g_Xb + (size_t)(m0 + row) * DK + kcol + w * 8;
            cp16_cg(sbase + row * 128 + ((w ^ (row & 7)) << 4), src);
        }
#pragma unroll
        for (int i = 0; i < 4; i++) {
            int v = tid + i * 256;
            int row = v >> 3, w = v & 7;
            const void* src = g_Wb + (size_t)(n0 + row) * DK + kcol + w * 8;
            cp16_cg(sbase + 16384 + row * 128 + ((w ^ (row & 7)) << 4), src);
        }
    };

    // ---- per-lane ldmatrix addressing ----
    const int g    = lid >> 3;                    // 0..3
    const int rsub = ((g & 1) << 3) + (lid & 7);  // row-in-16-tile
    const int whalf = g >> 1;                     // k-half word
    const int lsw  = lid & 7;                     // swizzle key

    uint32_t arow[4], brow[2];
#pragma unroll
    for (int i = 0; i < 4; i++) arow[i] = (mw * 64 + i * 16 + rsub) * 128;
#pragma unroll
    for (int j2 = 0; j2 < 2; j2++) brow[j2] = 16384u + (nw * 32 + j2 * 16 + rsub) * 128;

    // fp16x2 accumulators
    uint32_t acc[4][4][2];
#pragma unroll
    for (int i = 0; i < 4; i++)
#pragma unroll
        for (int j = 0; j < 4; j++) {
            acc[i][j][0] = 0u;
            acc[i][j][1] = 0u;
        }

    // ---- 3-stage pipelined main loop (one sync per chunk) ----
    load_chunk(0, 0); cp_commit();
    load_chunk(1, 1); cp_commit();

    for (int kc = 0; kc < NCHUNK; kc++) {
        cp_wait<1>();          // stage kc resident
        __syncthreads();       // all warps done reading stage (kc+2)%3
        if (kc + 2 < NCHUNK) {
            load_chunk(kc + 2, (kc + 2) % NSTAGE);
            cp_commit();
        }

        const uint32_t stage_base = sb + (kc % NSTAGE) * STAGE;
#pragma unroll
        for (int ks = 0; ks < 4; ks++) {
            const uint32_t wsw = (uint32_t)(((2 * ks + whalf) ^ lsw) << 4);
            uint32_t a[4][4], bf[2][4];
#pragma unroll
            for (int i = 0; i < 4; i++) ldsm_x4(a[i], stage_base + arow[i] + wsw);
#pragma unroll
            for (int j2 = 0; j2 < 2; j2++) ldsm_x4(bf[j2], stage_base + brow[j2] + wsw);
#pragma unroll
            for (int i = 0; i < 4; i++)
#pragma unroll
                for (int j = 0; j < 4; j++)
                    mma16816_f16(acc[i][j], a[i], bf[j >> 1][j & 1], bf[j >> 1][(j & 1) + 2]);
        }
    }
    __syncthreads();   // mainloop fully done before SMEM reuse

    // ---- epilogue: bias + sigmoid + lambda, reduce 2 rules in SMEM ----
    float* Ys    = (float*)smem;             // [128][64] fp32  (32KB)
    float* slam  = (float*)(smem + 32768);   // [128][2]
    float* sbias = (float*)(smem + 33792);   // [128]

    if (tid < 128) sbias[tid] = bias[n0 + tid];
    if (tid < 256) {
        int row = tid >> 1, r = tid & 1;
        slam[tid] = lambdas[(size_t)(m0 + row) * NRULES + rg * 2 + r];
    }
    __syncthreads();

    const int rule_half = nw >> 1;           // 0: cols 0-63, 1: cols 64-127
    const int lq = lid >> 2;                 // 0..7
    const int lr2 = (lid & 3) * 2;

    float lamv[4][2];
#pragma unroll
    for (int i = 0; i < 4; i++)
#pragma unroll
        for (int h = 0; h < 2; h++)
            lamv[i][h] = slam[(mw * 64 + i * 16 + lq + h * 8) * 2 + rule_half];

    float vals[4][4][4];
#pragma unroll
    for (int i = 0; i < 4; i++) {
#pragma unroll
        for (int j = 0; j < 4; j++) {
            int col = nw * 32 + j * 8 + lr2;
            float b0 = sbias[col], b1 = sbias[col + 1];
            float2 f01 = __half22float2(*(__half2*)&acc[i][j][0]);  // rows lq
            float2 f23 = __half22float2(*(__half2*)&acc[i][j][1]);  // rows lq+8
            vals[i][j][0] = lamv[i][0] * fast_sigmoid(f01.x + b0);
            vals[i][j][1] = lamv[i][0] * fast_sigmoid(f01.y + b1);
            vals[i][j][2] = lamv[i][1] * fast_sigmoid(f23.x + b0);
            vals[i][j][3] = lamv[i][1] * fast_sigmoid(f23.y + b1);
        }
    }

    // rule 0 warps store, rule 1 warps accumulate
    if (rule_half == 0) {
#pragma unroll
        for (int i = 0; i < 4; i++)
#pragma unroll
            for (int j = 0; j < 4; j++) {
                int row = mw * 64 + i * 16 + lq;
                int o = (nw & 1) * 32 + j * 8 + lr2;
                Ys[row * 64 + o]           = vals[i][j][0];
                Ys[row * 64 + o + 1]       = vals[i][j][1];
                Ys[(row + 8) * 64 + o]     = vals[i][j][2];
                Ys[(row + 8) * 64 + o + 1] = vals[i][j][3];
            }
    }
    __syncthreads();
    if (rule_half == 1) {
#pragma unroll
        for (int i = 0; i < 4; i++)
#pragma unroll
            for (int j = 0; j < 4; j++) {
                int row = mw * 64 + i * 16 + lq;
                int o = (nw & 1) * 32 + j * 8 + lr2;
                Ys[row * 64 + o]           += vals[i][j][0];
                Ys[row * 64 + o + 1]       += vals[i][j][1];
                Ys[(row + 8) * 64 + o]     += vals[i][j][2];
                Ys[(row + 8) * 64 + o + 1] += vals[i][j][3];
            }
    }
    __syncthreads();

    // write fp16 partials (4096 half2 per CTA)
    __half2* dst = (__half2*)(g_Ypart + ((size_t)rg * S_TOT + m0) * OPER);
    const float2* srcv = (const float2*)Ys;
#pragma unroll
    for (int v = 0; v < 16; v++) {
        float2 f = srcv[tid + v * 256];
        dst[tid + v * 256] = __float22half2_rn(f);
    }

    // ---- tail reduction: last CTA of this mtile reduces all 32 groups ----
    __shared__ int s_last;
    __syncthreads();                 // all partial stores issued
    if (tid == 0) {
        __threadfence();             // release: partials visible before count
        int c = atomicAdd(&g_cnt[blockIdx.x], 1);
        s_last = (c == NGRP - 1);
    }
    __syncthreads();
    if (s_last) {
        __threadfence();             // acquire: see all other CTAs' partials
        const int n8 = S_TOT * OPER / 8;          // uint4 stride per group
        const int tilebase8 = m0 * (OPER / 8);    // first uint4 of this tile
        const uint4* p = (const uint4*)g_Ypart;
#pragma unroll
        for (int v = 0; v < 4; v++) {
            int idx = tid + v * 256;              // 0..1023 within tile
            int i8 = tilebase8 + idx;
            float s[8];
#pragma unroll
            for (int k = 0; k < 8; k++) s[k] = 0.0f;
#pragma unroll
            for (int r = 0; r < NGRP; r++) {
                uint4 vv = p[(size_t)r * n8 + i8];
                const __half2* h = (const __half2*)&vv;
#pragma unroll
                for (int k = 0; k < 4; k++) {
                    float2 f = __half22float2(h[k]);
                    s[2 * k]     += f.x;
                    s[2 * k + 1] += f.y;
                }
            }
            float4* o = (float4*)(out + (size_t)i8 * 8);
            o[0] = make_float4(s[0], s[1], s[2], s[3]);
            o[1] = make_float4(s[4], s[5], s[6], s[7]);
        }
    }
}

// ---------------- launch ----------------
extern "C" void kernel_launch(void* const* d_in, const int* in_sizes, int n_in,
                              void* d_out, int out_size) {
    const float* X       = (const float*)d_in[0];  // [8192,1024]
    const float* W       = (const float*)d_in[1];  // [4096,1024]
    const float* b       = (const float*)d_in[2];  // [4096]
    const float* lambdas = (const float*)d_in[3];  // [8192,64]
    float* out = (float*)d_out;

    cudaFuncSetAttribute(somfnn_gemm, cudaFuncAttributeMaxDynamicSharedMemorySize, SMEM_SZ);

    cvt_kernel<<<CVT_BLOCKS, 256>>>((const float4*)X, (const float4*)W);

    dim3 grid(MTILES, NGRP);
    somfnn_gemm<<<grid, 256, SMEM_SZ>>>(b, lambdas, out);
}

// round 16
// speedup vs baseline: 1.0277x; 1.0277x over previous
#include <cuda_runtime.h>
#include <cuda_bf16.h>
#include <cuda_fp16.h>
#include <cstdint>

// ---------------- problem constants ----------------
#define S_TOT   8192
#define DK      1024            // K
#define NRULES  64
#define OPER    64
#define RO      (NRULES*OPER)   // 4096

// ---------------- tiling ----------------
#define BM      128             // CTA M tile
#define BN      128             // CTA N tile (= 2 rules)
#define KC      64              // K per chunk (fp16)
#define NCHUNK  (DK/KC)         // 16
#define NGRP    (RO/BN)         // 32 rule-groups
#define MTILES  (S_TOT/BM)      // 64
#define NSTAGE  3
#define STAGE   32768           // bytes per stage (A 16K + B 16K)
#define SMEM_SZ (NSTAGE*STAGE)  // 98304 -> 2 CTAs/SM

// ---------------- scratch ----------------
__device__ __half g_Xb[(size_t)S_TOT*DK];            // 16 MB (fp16)
__device__ __half g_Wb[(size_t)RO*DK];               // 8 MB  (fp16)
__device__ __half g_Ypart[(size_t)NGRP*S_TOT*OPER];  // 32 MB (fp16 partials)
__device__ int    g_cnt[MTILES];                     // per-mtile arrival counter

// ---------------- helpers ----------------
__device__ __forceinline__ uint32_t smem_u32(const void* p) {
    uint32_t a;
    asm("{ .reg .u64 t; cvta.to.shared.u64 t, %1; cvt.u32.u64 %0, t; }" : "=r"(a) : "l"(p));
    return a;
}
__device__ __forceinline__ void cp16_cg(uint32_t dst, const void* src) {   // L1 bypass
    asm volatile("cp.async.cg.shared.global [%0], [%1], 16;" :: "r"(dst), "l"(src));
}
__device__ __forceinline__ void cp_commit() {
    asm volatile("cp.async.commit_group;" ::: "memory");
}
template <int N>
__device__ __forceinline__ void cp_wait() {
    asm volatile("cp.async.wait_group %0;" :: "n"(N) : "memory");
}
__device__ __forceinline__ void ldsm_x4(uint32_t* r, uint32_t addr) {
    asm volatile("ldmatrix.sync.aligned.m8n8.x4.shared.b16 {%0,%1,%2,%3}, [%4];"
        : "=r"(r[0]), "=r"(r[1]), "=r"(r[2]), "=r"(r[3]) : "r"(addr));
}
// fp16-accumulate HMMA: D,C are 2x .f16x2 regs
__device__ __forceinline__ void mma16816_f16(uint32_t* c, const uint32_t* a,
                                             uint32_t b0, uint32_t b1) {
    asm volatile("mma.sync.aligned.m16n8k16.row.col.f16.f16.f16.f16 "
        "{%0,%1}, {%2,%3,%4,%5}, {%6,%7}, {%0,%1};"
        : "+r"(c[0]), "+r"(c[1])
        : "r"(a[0]), "r"(a[1]), "r"(a[2]), "r"(a[3]), "r"(b0), "r"(b1));
}
// sigmoid(x) = 0.5*tanh(0.5x) + 0.5  -> 1 MUFU + FMA
__device__ __forceinline__ float fast_sigmoid(float x) {
    float t;
    float h = 0.5f * x;
    asm("tanh.approx.f32 %0, %1;" : "=f"(t) : "f"(h));
    return fmaf(0.5f, t, 0.5f);
}

// ---------------- conversion kernel (fp32 -> fp16, MLP=8) ----------------
#define NX4 ((size_t)S_TOT*DK/4)       // 2097152 float4 in X
#define NW4 ((size_t)RO*DK/4)          // 1048576 float4 in W
#define WX_CVT (NX4/256)               // 8192 warps for X
#define WW_CVT (NW4/256)               // 4096 warps for W
#define CVT_BLOCKS ((unsigned)((WX_CVT + WW_CVT) / 8))   // 1536 blocks of 8 warps

__device__ __forceinline__ uint32_t pack_h2(float a, float b) {
    __half2 h = __floats2half2_rn(a, b);
    return *(uint32_t*)&h;
}
__global__ void __launch_bounds__(256)
cvt_kernel(const float4* __restrict__ X4, const float4* __restrict__ W4) {
    // reset the per-mtile arrival counters for this launch / graph replay
    if (blockIdx.x == 0 && threadIdx.x < MTILES) g_cnt[threadIdx.x] = 0;

    size_t t = (size_t)blockIdx.x * 256 + threadIdx.x;
    size_t w = t >> 5;
    int lane = (int)(t & 31);
    const float4* src;
    __half* dst;
    size_t base;
    if (w < WX_CVT) { src = X4; dst = g_Xb; base = w * 256; }
    else            { src = W4; dst = g_Wb; base = (w - WX_CVT) * 256; }

    float4 v[8];
#pragma unroll
    for (int i = 0; i < 8; i++) v[i] = src[base + lane + 32 * i];

    uint2* d = (uint2*)dst;   // uint2 index == float4 index
#pragma unroll
    for (int i = 0; i < 8; i++) {
        uint2 o;
        o.x = pack_h2(v[i].x, v[i].y);
        o.y = pack_h2(v[i].z, v[i].w);
        d[base + lane + 32 * i] = o;
    }
}

// ---------------- fused GEMM + sigmoid + lambda + tail reduction ----------------
__global__ void __launch_bounds__(256, 2)
somfnn_gemm(const float* __restrict__ bias, const float* __restrict__ lambdas,
            float* __restrict__ out) {
    extern __shared__ __align__(1024) char smem[];
    const uint32_t sb = smem_u32(smem);
    const int tid = threadIdx.x;
    const int wid = tid >> 5;
    const int lid = tid & 31;
    const int mw  = wid >> 2;        // 0..1 (M warps)
    const int nw  = wid & 3;         // 0..3 (N warps)
    const int m0  = blockIdx.x * BM;
    const int rg  = blockIdx.y;      // 0..31
    const int n0  = rg * BN;

    // ---- hoisted cp.async addressing ----
    // v = tid + i*256  =>  row = (tid>>3) + 32*i,  w = tid&7,  (row&7) == ((tid>>3)&7)
    // global: base + i*32*DK*2 bytes (compile-time imm); advance base by KC*2 per chunk
    // smem:   dstbase + i*4096 (+16384 for B), swizzle i-invariant
    const int trow = tid >> 3;            // 0..31
    const int tw   = tid & 7;             // 0..7
    const char* srcA = (const char*)(g_Xb + (size_t)(m0 + trow) * DK) + tw * 16;
    const char* srcB = (const char*)(g_Wb + (size_t)(n0 + trow) * DK) + tw * 16;
    const uint32_t dstA = (uint32_t)(trow * 128 + ((tw ^ (trow & 7)) << 4));
    const uint32_t dstB = dstA + 16384u;

    auto load_chunk = [&](const char* sA, const char* sB, int buf) {
        const uint32_t sbase = sb + buf * STAGE;
#pragma unroll
        for (int i = 0; i < 4; i++)
            cp16_cg(sbase + dstA + i * 4096, sA + (size_t)i * (32 * DK * 2));
#pragma unroll
        for (int i = 0; i < 4; i++)
            cp16_cg(sbase + dstB + i * 4096, sB + (size_t)i * (32 * DK * 2));
    };

    // ---- per-lane ldmatrix addressing ----
    const int g    = lid >> 3;                    // 0..3
    const int rsub = ((g & 1) << 3) + (lid & 7);  // row-in-16-tile
    const int whalf = g >> 1;                     // k-half word
    const int lsw  = lid & 7;                     // swizzle key

    uint32_t arow[4], brow[2];
#pragma unroll
    for (int i = 0; i < 4; i++) arow[i] = (mw * 64 + i * 16 + rsub) * 128;
#pragma unroll
    for (int j2 = 0; j2 < 2; j2++) brow[j2] = 16384u + (nw * 32 + j2 * 16 + rsub) * 128;

    // precomputed per-ks swizzle offsets (per-thread constants)
    uint32_t wswv[4];
#pragma unroll
    for (int ks = 0; ks < 4; ks++)
        wswv[ks] = (uint32_t)(((2 * ks + whalf) ^ lsw) << 4);

    // fp16x2 accumulators
    uint32_t acc[4][4][2];
#pragma unroll
    for (int i = 0; i < 4; i++)
#pragma unroll
        for (int j = 0; j < 4; j++) {
            acc[i][j][0] = 0u;
            acc[i][j][1] = 0u;
        }

    // ---- 3-stage pipelined main loop (one sync per chunk) ----
    load_chunk(srcA, srcB, 0); cp_commit();
    load_chunk(srcA + KC * 2, srcB + KC * 2, 1); cp_commit();

    for (int kc = 0; kc < NCHUNK; kc++) {
        cp_wait<1>();          // stage kc resident
        __syncthreads();       // all warps done reading stage (kc+2)%3
        if (kc + 2 < NCHUNK) {
            load_chunk(srcA + (size_t)(kc + 2) * (KC * 2),
                       srcB + (size_t)(kc + 2) * (KC * 2),
                       (kc + 2) % NSTAGE);
            cp_commit();
        }

        const uint32_t stage_base = sb + (kc % NSTAGE) * STAGE;
#pragma unroll
        for (int ks = 0; ks < 4; ks++) {
            const uint32_t wsw = wswv[ks];
            uint32_t a[4][4], bf[2][4];
#pragma unroll
            for (int i = 0; i < 4; i++) ldsm_x4(a[i], stage_base + arow[i] + wsw);
#pragma unroll
            for (int j2 = 0; j2 < 2; j2++) ldsm_x4(bf[j2], stage_base + brow[j2] + wsw);
#pragma unroll
            for (int i = 0; i < 4; i++)
#pragma unroll
                for (int j = 0; j < 4; j++)
                    mma16816_f16(acc[i][j], a[i], bf[j >> 1][j & 1], bf[j >> 1][(j & 1) + 2]);
        }
    }
    __syncthreads();   // mainloop fully done before SMEM reuse

    // ---- epilogue: bias + sigmoid + lambda, reduce 2 rules in SMEM ----
    float* Ys    = (float*)smem;             // [128][64] fp32  (32KB)
    float* slam  = (float*)(smem + 32768);   // [128][2]
    float* sbias = (float*)(smem + 33792);   // [128]

    if (tid < 128) sbias[tid] = bias[n0 + tid];
    if (tid < 256) {
        int row = tid >> 1, r = tid & 1;
        slam[tid] = lambdas[(size_t)(m0 + row) * NRULES + rg * 2 + r];
    }
    __syncthreads();

    const int rule_half = nw >> 1;           // 0: cols 0-63, 1: cols 64-127
    const int lq = lid >> 2;                 // 0..7
    const int lr2 = (lid & 3) * 2;

    float lamv[4][2];
#pragma unroll
    for (int i = 0; i < 4; i++)
#pragma unroll
        for (int h = 0; h < 2; h++)
            lamv[i][h] = slam[(mw * 64 + i * 16 + lq + h * 8) * 2 + rule_half];

    float vals[4][4][4];
#pragma unroll
    for (int i = 0; i < 4; i++) {
#pragma unroll
        for (int j = 0; j < 4; j++) {
            int col = nw * 32 + j * 8 + lr2;
            float b0 = sbias[col], b1 = sbias[col + 1];
            float2 f01 = __half22float2(*(__half2*)&acc[i][j][0]);  // rows lq
            float2 f23 = __half22float2(*(__half2*)&acc[i][j][1]);  // rows lq+8
            vals[i][j][0] = lamv[i][0] * fast_sigmoid(f01.x + b0);
            vals[i][j][1] = lamv[i][0] * fast_sigmoid(f01.y + b1);
            vals[i][j][2] = lamv[i][1] * fast_sigmoid(f23.x + b0);
            vals[i][j][3] = lamv[i][1] * fast_sigmoid(f23.y + b1);
        }
    }

    // rule 0 warps store, rule 1 warps accumulate
    if (rule_half == 0) {
#pragma unroll
        for (int i = 0; i < 4; i++)
#pragma unroll
            for (int j = 0; j < 4; j++) {
                int row = mw * 64 + i * 16 + lq;
                int o = (nw & 1) * 32 + j * 8 + lr2;
                Ys[row * 64 + o]           = vals[i][j][0];
                Ys[row * 64 + o + 1]       = vals[i][j][1];
                Ys[(row + 8) * 64 + o]     = vals[i][j][2];
                Ys[(row + 8) * 64 + o + 1] = vals[i][j][3];
            }
    }
    __syncthreads();
    if (rule_half == 1) {
#pragma unroll
        for (int i = 0; i < 4; i++)
#pragma unroll
            for (int j = 0; j < 4; j++) {
                int row = mw * 64 + i * 16 + lq;
                int o = (nw & 1) * 32 + j * 8 + lr2;
                Ys[row * 64 + o]           += vals[i][j][0];
                Ys[row * 64 + o + 1]       += vals[i][j][1];
                Ys[(row + 8) * 64 + o]     += vals[i][j][2];
                Ys[(row + 8) * 64 + o + 1] += vals[i][j][3];
            }
    }
    __syncthreads();

    // write fp16 partials (4096 half2 per CTA)
    __half2* dst = (__half2*)(g_Ypart + ((size_t)rg * S_TOT + m0) * OPER);
    const float2* srcv = (const float2*)Ys;
#pragma unroll
    for (int v = 0; v < 16; v++) {
        float2 f = srcv[tid + v * 256];
        dst[tid + v * 256] = __float22half2_rn(f);
    }

    // ---- tail reduction: last CTA of this mtile reduces all 32 groups ----
    __shared__ int s_last;
    __syncthreads();                 // all partial stores issued
    if (tid == 0) {
        __threadfence();             // release: partials visible before count
        int c = atomicAdd(&g_cnt[blockIdx.x], 1);
        s_last = (c == NGRP - 1);
    }
    __syncthreads();
    if (s_last) {
        __threadfence();             // acquire: see all other CTAs' partials
        const int n8 = S_TOT * OPER / 8;          // uint4 stride per group
        const int tilebase8 = m0 * (OPER / 8);    // first uint4 of this tile
        const uint4* p = (const uint4*)g_Ypart;
#pragma unroll
        for (int v = 0; v < 4; v++) {
            int idx = tid + v * 256;              // 0..1023 within tile
            int i8 = tilebase8 + idx;
            float s[8];
#pragma unroll
            for (int k = 0; k < 8; k++) s[k] = 0.0f;
#pragma unroll
            for (int r = 0; r < NGRP; r++) {
                uint4 vv = p[(size_t)r * n8 + i8];
                const __half2* h = (const __half2*)&vv;
#pragma unroll
                for (int k = 0; k < 4; k++) {
                    float2 f = __half22float2(h[k]);
                    s[2 * k]     += f.x;
                    s[2 * k + 1] += f.y;
                }
            }
            float4* o = (float4*)(out + (size_t)i8 * 8);
            o[0] = make_float4(s[0], s[1], s[2], s[3]);
            o[1] = make_float4(s[4], s[5], s[6], s[7]);
        }
    }
}

// ---------------- launch ----------------
extern "C" void kernel_launch(void* const* d_in, const int* in_sizes, int n_in,
                              void* d_out, int out_size) {
    const float* X       = (const float*)d_in[0];  // [8192,1024]
    const float* W       = (const float*)d_in[1];  // [4096,1024]
    const float* b       = (const float*)d_in[2];  // [4096]
    const float* lambdas = (const float*)d_in[3];  // [8192,64]
    float* out = (float*)d_out;

    cudaFuncSetAttribute(somfnn_gemm, cudaFuncAttributeMaxDynamicSharedMemorySize, SMEM_SZ);

    cvt_kernel<<<CVT_BLOCKS, 256>>>((const float4*)X, (const float4*)W);

    dim3 grid(MTILES, NGRP);
    somfnn_gemm<<<grid, 256, SMEM_SZ>>>(b, lambdas, out);
}

// round 17
// speedup vs baseline: 1.0280x; 1.0003x over previous
#include <cuda_runtime.h>
#include <cuda_bf16.h>
#include <cuda_fp16.h>
#include <cstdint>

// ---------------- problem constants ----------------
#define S_TOT   8192
#define DK      1024            // K
#define NRULES  64
#define OPER    64
#define RO      (NRULES*OPER)   // 4096

// ---------------- tiling ----------------
#define BM      128             // CTA M tile
#define BN      128             // CTA N tile (= 2 rules)
#define KC      64              // K per chunk (fp16)
#define NCHUNK  (DK/KC)         // 16
#define NGRP    (RO/BN)         // 32 rule-groups
#define MTILES  (S_TOT/BM)      // 64
#define NSTAGE  3
#define STAGE   32768           // bytes per stage (A 16K + B 16K)
#define SMEM_SZ (NSTAGE*STAGE)  // 98304 -> 2 CTAs/SM

// ---------------- scratch ----------------
__device__ __half g_Xb[(size_t)S_TOT*DK];            // 16 MB (fp16)
__device__ __half g_Wb[(size_t)RO*DK];               // 8 MB  (fp16)
__device__ __half g_Ypart[(size_t)NGRP*S_TOT*OPER];  // 32 MB (fp16 partials)
__device__ int    g_cnt[MTILES];                     // per-mtile arrival counter

// ---------------- helpers ----------------
__device__ __forceinline__ uint32_t smem_u32(const void* p) {
    uint32_t a;
    asm("{ .reg .u64 t; cvta.to.shared.u64 t, %1; cvt.u32.u64 %0, t; }" : "=r"(a) : "l"(p));
    return a;
}
__device__ __forceinline__ void cp16_cg(uint32_t dst, const void* src) {   // L1 bypass
    asm volatile("cp.async.cg.shared.global [%0], [%1], 16;" :: "r"(dst), "l"(src));
}
__device__ __forceinline__ void cp_commit() {
    asm volatile("cp.async.commit_group;" ::: "memory");
}
template <int N>
__device__ __forceinline__ void cp_wait() {
    asm volatile("cp.async.wait_group %0;" :: "n"(N) : "memory");
}
__device__ __forceinline__ void ldsm_x4(uint32_t* r, uint32_t addr) {
    asm volatile("ldmatrix.sync.aligned.m8n8.x4.shared.b16 {%0,%1,%2,%3}, [%4];"
        : "=r"(r[0]), "=r"(r[1]), "=r"(r[2]), "=r"(r[3]) : "r"(addr));
}
// fp16-accumulate HMMA: D,C are 2x .f16x2 regs
__device__ __forceinline__ void mma16816_f16(uint32_t* c, const uint32_t* a,
                                             uint32_t b0, uint32_t b1) {
    asm volatile("mma.sync.aligned.m16n8k16.row.col.f16.f16.f16.f16 "
        "{%0,%1}, {%2,%3,%4,%5}, {%6,%7}, {%0,%1};"
        : "+r"(c[0]), "+r"(c[1])
        : "r"(a[0]), "r"(a[1]), "r"(a[2]), "r"(a[3]), "r"(b0), "r"(b1));
}
// sigmoid(x) = 0.5*tanh(0.5x) + 0.5  -> 1 MUFU + FMA
__device__ __forceinline__ float fast_sigmoid(float x) {
    float t;
    float h = 0.5f * x;
    asm("tanh.approx.f32 %0, %1;" : "=f"(t) : "f"(h));
    return fmaf(0.5f, t, 0.5f);
}

// ---------------- conversion kernel (fp32 -> fp16, MLP=8) ----------------
#define NX4 ((size_t)S_TOT*DK/4)       // 2097152 float4 in X
#define NW4 ((size_t)RO*DK/4)          // 1048576 float4 in W
#define WX_CVT (NX4/256)               // 8192 warps for X
#define WW_CVT (NW4/256)               // 4096 warps for W
#define CVT_BLOCKS ((unsigned)((WX_CVT + WW_CVT) / 8))   // 1536 blocks of 8 warps

__device__ __forceinline__ uint32_t pack_h2(float a, float b) {
    __half2 h = __floats2half2_rn(a, b);
    return *(uint32_t*)&h;
}
__global__ void __launch_bounds__(256)
cvt_kernel(const float4* __restrict__ X4, const float4* __restrict__ W4) {
    // reset the per-mtile arrival counters for this launch / graph replay
    if (blockIdx.x == 0 && threadIdx.x < MTILES) g_cnt[threadIdx.x] = 0;

    size_t t = (size_t)blockIdx.x * 256 + threadIdx.x;
    size_t w = t >> 5;
    int lane = (int)(t & 31);
    const float4* src;
    __half* dst;
    size_t base;
    if (w < WX_CVT) { src = X4; dst = g_Xb; base = w * 256; }
    else            { src = W4; dst = g_Wb; base = (w - WX_CVT) * 256; }

    float4 v[8];
#pragma unroll
    for (int i = 0; i < 8; i++) v[i] = __ldcs(&src[base + lane + 32 * i]);  // streaming read-once

    uint2* d = (uint2*)dst;   // uint2 index == float4 index
#pragma unroll
    for (int i = 0; i < 8; i++) {
        uint2 o;
        o.x = pack_h2(v[i].x, v[i].y);
        o.y = pack_h2(v[i].z, v[i].w);
        d[base + lane + 32 * i] = o;
    }

    // PDL: allow the dependent GEMM grid to begin launching; its
    // cudaGridDependencySynchronize still waits for full completion/visibility.
    cudaTriggerProgrammaticLaunchCompletion();
}

// ---------------- fused GEMM + sigmoid + lambda + tail reduction ----------------
__global__ void __launch_bounds__(256, 2)
somfnn_gemm(const float* __restrict__ bias, const float* __restrict__ lambdas,
            float* __restrict__ out) {
    extern __shared__ __align__(1024) char smem[];
    const uint32_t sb = smem_u32(smem);
    const int tid = threadIdx.x;
    const int wid = tid >> 5;
    const int lid = tid & 31;
    const int mw  = wid >> 2;        // 0..1 (M warps)
    const int nw  = wid & 3;         // 0..3 (N warps)
    const int m0  = blockIdx.x * BM;
    const int rg  = blockIdx.y;      // 0..31
    const int n0  = rg * BN;

    // ---- hoisted cp.async addressing (independent of cvt results) ----
    const int trow = tid >> 3;            // 0..31
    const int tw   = tid & 7;             // 0..7
    const char* srcA = (const char*)(g_Xb + (size_t)(m0 + trow) * DK) + tw * 16;
    const char* srcB = (const char*)(g_Wb + (size_t)(n0 + trow) * DK) + tw * 16;
    const uint32_t dstA = (uint32_t)(trow * 128 + ((tw ^ (trow & 7)) << 4));
    const uint32_t dstB = dstA + 16384u;

    auto load_chunk = [&](const char* sA, const char* sB, int buf) {
        const uint32_t sbase = sb + buf * STAGE;
#pragma unroll
        for (int i = 0; i < 4; i++)
            cp16_cg(sbase + dstA + i * 4096, sA + (size_t)i * (32 * DK * 2));
#pragma unroll
        for (int i = 0; i < 4; i++)
            cp16_cg(sbase + dstB + i * 4096, sB + (size_t)i * (32 * DK * 2));
    };

    // ---- per-lane ldmatrix addressing ----
    const int g    = lid >> 3;                    // 0..3
    const int rsub = ((g & 1) << 3) + (lid & 7);  // row-in-16-tile
    const int whalf = g >> 1;                     // k-half word
    const int lsw  = lid & 7;                     // swizzle key

    uint32_t arow[4], brow[2];
#pragma unroll
    for (int i = 0; i < 4; i++) arow[i] = (mw * 64 + i * 16 + rsub) * 128;
#pragma unroll
    for (int j2 = 0; j2 < 2; j2++) brow[j2] = 16384u + (nw * 32 + j2 * 16 + rsub) * 128;

    uint32_t wswv[4];
#pragma unroll
    for (int ks = 0; ks < 4; ks++)
        wswv[ks] = (uint32_t)(((2 * ks + whalf) ^ lsw) << 4);

    // fp16x2 accumulators
    uint32_t acc[4][4][2];
#pragma unroll
    for (int i = 0; i < 4; i++)
#pragma unroll
        for (int j = 0; j < 4; j++) {
            acc[i][j][0] = 0u;
            acc[i][j][1] = 0u;
        }

    // PDL: wait for cvt grid completion (g_Xb/g_Wb/g_cnt visible) before
    // the first global read. Everything above overlapped with cvt's tail.
    cudaGridDependencySynchronize();

    // ---- 3-stage pipelined main loop (one sync per chunk) ----
    load_chunk(srcA, srcB, 0); cp_commit();
    load_chunk(srcA + KC * 2, srcB + KC * 2, 1); cp_commit();

    for (int kc = 0; kc < NCHUNK; kc++) {
        cp_wait<1>();          // stage kc resident
        __syncthreads();       // all warps done reading stage (kc+2)%3
        if (kc + 2 < NCHUNK) {
            load_chunk(srcA + (size_t)(kc + 2) * (KC * 2),
                       srcB + (size_t)(kc + 2) * (KC * 2),
                       (kc + 2) % NSTAGE);
            cp_commit();
        }

        const uint32_t stage_base = sb + (kc % NSTAGE) * STAGE;
#pragma unroll
        for (int ks = 0; ks < 4; ks++) {
            const uint32_t wsw = wswv[ks];
            uint32_t a[4][4], bf[2][4];
#pragma unroll
            for (int i = 0; i < 4; i++) ldsm_x4(a[i], stage_base + arow[i] + wsw);
#pragma unroll
            for (int j2 = 0; j2 < 2; j2++) ldsm_x4(bf[j2], stage_base + brow[j2] + wsw);
#pragma unroll
            for (int i = 0; i < 4; i++)
#pragma unroll
                for (int j = 0; j < 4; j++)
                    mma16816_f16(acc[i][j], a[i], bf[j >> 1][j & 1], bf[j >> 1][(j & 1) + 2]);
        }
    }
    __syncthreads();   // mainloop fully done before SMEM reuse

    // ---- epilogue: bias + sigmoid + lambda, reduce 2 rules in SMEM ----
    float* Ys    = (float*)smem;             // [128][64] fp32  (32KB)
    float* slam  = (float*)(smem + 32768);   // [128][2]
    float* sbias = (float*)(smem + 33792);   // [128]

    if (tid < 128) sbias[tid] = bias[n0 + tid];
    if (tid < 256) {
        int row = tid >> 1, r = tid & 1;
        slam[tid] = lambdas[(size_t)(m0 + row) * NRULES + rg * 2 + r];
    }
    __syncthreads();

    const int rule_half = nw >> 1;           // 0: cols 0-63, 1: cols 64-127
    const int lq = lid >> 2;                 // 0..7
    const int lr2 = (lid & 3) * 2;

    float lamv[4][2];
#pragma unroll
    for (int i = 0; i < 4; i++)
#pragma unroll
        for (int h = 0; h < 2; h++)
            lamv[i][h] = slam[(mw * 64 + i * 16 + lq + h * 8) * 2 + rule_half];

    float vals[4][4][4];
#pragma unroll
    for (int i = 0; i < 4; i++) {
#pragma unroll
        for (int j = 0; j < 4; j++) {
            int col = nw * 32 + j * 8 + lr2;
            float b0 = sbias[col], b1 = sbias[col + 1];
            float2 f01 = __half22float2(*(__half2*)&acc[i][j][0]);  // rows lq
            float2 f23 = __half22float2(*(__half2*)&acc[i][j][1]);  // rows lq+8
            vals[i][j][0] = lamv[i][0] * fast_sigmoid(f01.x + b0);
            vals[i][j][1] = lamv[i][0] * fast_sigmoid(f01.y + b1);
            vals[i][j][2] = lamv[i][1] * fast_sigmoid(f23.x + b0);
            vals[i][j][3] = lamv[i][1] * fast_sigmoid(f23.y + b1);
        }
    }

    // rule 0 warps store, rule 1 warps accumulate
    if (rule_half == 0) {
#pragma unroll
        for (int i = 0; i < 4; i++)
#pragma unroll
            for (int j = 0; j < 4; j++) {
                int row = mw * 64 + i * 16 + lq;
                int o = (nw & 1) * 32 + j * 8 + lr2;
                Ys[row * 64 + o]           = vals[i][j][0];
                Ys[row * 64 + o + 1]       = vals[i][j][1];
                Ys[(row + 8) * 64 + o]     = vals[i][j][2];
                Ys[(row + 8) * 64 + o + 1] = vals[i][j][3];
            }
    }
    __syncthreads();
    if (rule_half == 1) {
#pragma unroll
        for (int i = 0; i < 4; i++)
#pragma unroll
            for (int j = 0; j < 4; j++) {
                int row = mw * 64 + i * 16 + lq;
                int o = (nw & 1) * 32 + j * 8 + lr2;
                Ys[row * 64 + o]           += vals[i][j][0];
                Ys[row * 64 + o + 1]       += vals[i][j][1];
                Ys[(row + 8) * 64 + o]     += vals[i][j][2];
                Ys[(row + 8) * 64 + o + 1] += vals[i][j][3];
            }
    }
    __syncthreads();

    // write fp16 partials (4096 half2 per CTA)
    __half2* dst = (__half2*)(g_Ypart + ((size_t)rg * S_TOT + m0) * OPER);
    const float2* srcv = (const float2*)Ys;
#pragma unroll
    for (int v = 0; v < 16; v++) {
        float2 f = srcv[tid + v * 256];
        dst[tid + v * 256] = __float22half2_rn(f);
    }

    // ---- tail reduction: last CTA of this mtile reduces all 32 groups ----
    __shared__ int s_last;
    __syncthreads();                 // all partial stores issued
    if (tid == 0) {
        __threadfence();             // release: partials visible before count
        int c = atomicAdd(&g_cnt[blockIdx.x], 1);
        s_last = (c == NGRP - 1);
    }
    __syncthreads();
    if (s_last) {
        __threadfence();             // acquire: see all other CTAs' partials
        const int n8 = S_TOT * OPER / 8;          // uint4 stride per group
        const int tilebase8 = m0 * (OPER / 8);    // first uint4 of this tile
        const uint4* p = (const uint4*)g_Ypart;
#pragma unroll
        for (int v = 0; v < 4; v++) {
            int idx = tid + v * 256;              // 0..1023 within tile
            int i8 = tilebase8 + idx;
            float s[8];
#pragma unroll
            for (int k = 0; k < 8; k++) s[k] = 0.0f;
#pragma unroll
            for (int r = 0; r < NGRP; r++) {
                uint4 vv = p[(size_t)r * n8 + i8];
                const __half2* h = (const __half2*)&vv;
#pragma unroll
                for (int k = 0; k < 4; k++) {
                    float2 f = __half22float2(h[k]);
                    s[2 * k]     += f.x;
                    s[2 * k + 1] += f.y;
                }
            }
            float4* o = (float4*)(out + (size_t)i8 * 8);
            o[0] = make_float4(s[0], s[1], s[2], s[3]);
            o[1] = make_float4(s[4], s[5], s[6], s[7]);
        }
    }
}

// ---------------- launch ----------------
extern "C" void kernel_launch(void* const* d_in, const int* in_sizes, int n_in,
                              void* d_out, int out_size) {
    const float* X       = (const float*)d_in[0];  // [8192,1024]
    const float* W       = (const float*)d_in[1];  // [4096,1024]
    const float* b       = (const float*)d_in[2];  // [4096]
    const float* lambdas = (const float*)d_in[3];  // [8192,64]
    float* out = (float*)d_out;

    cudaFuncSetAttribute(somfnn_gemm, cudaFuncAttributeMaxDynamicSharedMemorySize, SMEM_SZ);

    cvt_kernel<<<CVT_BLOCKS, 256>>>((const float4*)X, (const float4*)W);

    // PDL launch: GEMM may begin launching as soon as cvt triggers completion;
    // its cudaGridDependencySynchronize gates all global reads.
    cudaLaunchConfig_t cfg = {};
    cfg.gridDim = dim3(MTILES, NGRP);
    cfg.blockDim = dim3(256);
    cfg.dynamicSmemBytes = SMEM_SZ;
    cfg.stream = 0;
    cudaLaunchAttribute attr[1];
    attr[0].id = cudaLaunchAttributeProgrammaticStreamSerialization;
    attr[0].val.programmaticStreamSerializationAllowed = 1;
    cfg.attrs = attr;
    cfg.numAttrs = 1;
    cudaLaunchKernelEx(&cfg, somfnn_gemm, (const float*)b, (const float*)lambdas, out);
}